// round 17
// baseline (speedup 1.0000x reference)
#include <cuda_runtime.h>
#include <cuda_fp16.h>
#include <cuda_bf16.h>

// Problem shapes (fixed by the dataset):
//   text:        [16, 2048, 256] f32      d_in[0]
//   const_mat:   [16, 2048, 2048] i32     d_in[1]   (UNUSED: softmax rows sum to 1)
//   const_labels:[16, 2048, 8] i32        d_in[2]
//   emb_table:   [100, 128] f32           d_in[3]
//   attn_W:      [256, 384] f32           d_in[4]   (UNUSED: cancels in softmax)
//   attn_b:      [256] f32                d_in[5]   (UNUSED)
//   fc_W:        [256, 128] f32           d_in[6]
//   fc_b:        [256] f32                d_in[7]
//   out:         [16, 2048, 256] f32
//
// Collapse: out[pos,d] = relu( text[pos,d] + sum_{k=0..7} G[labels[pos,k], d] )
// with G[n,d] = 0.125 * (fc_b[d] + emb_table[n] . fc_W[d]), G stored fp16.
//
// R17 = R16 (best, 16.86us) + (a) full-fp16 balanced reduction tree: 7 HADD2
// + 1 F2F per half2-slot instead of 4 HADD2 + 4 F2F + 6 FADD (-17% issue
// work per warp; issue was 39.5% with neither pipe saturated), (b) 128-thread
// CTAs at 12 CTAs/SM: same 1536 thr/SM but half the tail-quantization granule
// over the 4.6-wave grid.

#define CN    100
#define CD    128
#define DIM   256
#define KLBL  8

__device__ __half g_Gh[CN * DIM];  // 50 KB fp16 table

// ---------------------------------------------------------------------------
// Kernel A: G[n,d] = 0.125 * (fc_b[d] + sum_c emb_table[n,c] * fc_W[d,c])
// grid = (CN, 4), block = 256. Warp computes one (n,d) per iteration, lanes
// spanning c. All fc_W traffic coalesced.
// ---------------------------------------------------------------------------
__global__ void __launch_bounds__(256) build_G_kernel(
    const float* __restrict__ emb_table,
    const float* __restrict__ fc_W,
    const float* __restrict__ fc_b)
{
    const int n   = blockIdx.x;
    const int tid = threadIdx.x;

    __shared__ float4 se4[CD / 4];   // emb row n as float4
    if (tid < CD / 4)
        se4[tid] = reinterpret_cast<const float4*>(emb_table + n * CD)[tid];
    __syncthreads();

    const int warp = tid >> 5;
    const int lane = tid & 31;
    const float4 e = se4[lane];      // lane's c-chunk (conflict-free LDS)

    const float4* W4 = reinterpret_cast<const float4*>(fc_W);

    #pragma unroll
    for (int i = 0; i < 8; i++) {
        const int d = (blockIdx.y << 6) + (i << 3) + warp;   // 0..255

        // Coalesced: lane reads fc_W[d, 4*lane .. 4*lane+3].
        const float4 w = __ldg(W4 + d * 32 + lane);
        float p = w.x * e.x + w.y * e.y + w.z * e.z + w.w * e.w;

        p += __shfl_xor_sync(0xFFFFFFFFu, p, 16);
        p += __shfl_xor_sync(0xFFFFFFFFu, p, 8);
        p += __shfl_xor_sync(0xFFFFFFFFu, p, 4);
        p += __shfl_xor_sync(0xFFFFFFFFu, p, 2);
        p += __shfl_xor_sync(0xFFFFFFFFu, p, 1);

        if (lane == 0)
            g_Gh[n * DIM + d] = __float2half_rn(0.125f * (p + __ldg(fc_b + d)));
    }
}

// ---------------------------------------------------------------------------
// Kernel B: fused gather-add-relu. gid -> pos = gid>>5, d4 = gid&31.
// Thread covers output float4s (pos, d4) and (pos, d4+32).
// ---------------------------------------------------------------------------
__device__ __forceinline__ __half2 as_h2(unsigned u) {
    return *reinterpret_cast<const __half2*>(&u);
}

// ld.global.lu float4: last-use in L1 (evict-first locally), default L2.
__device__ __forceinline__ float4 ldlu_f4(const float4* p) {
    float4 v;
    asm volatile("ld.global.lu.v4.f32 {%0,%1,%2,%3}, [%4];"
                 : "=f"(v.x), "=f"(v.y), "=f"(v.z), "=f"(v.w)
                 : "l"(p));
    return v;
}

// Full-fp16 balanced tree over 8 half2 values, one convert at the end.
__device__ __forceinline__ float2 tree8_h2(
    __half2 v0, __half2 v1, __half2 v2, __half2 v3,
    __half2 v4, __half2 v5, __half2 v6, __half2 v7)
{
    const __half2 p0 = __hadd2(v0, v1);
    const __half2 p1 = __hadd2(v2, v3);
    const __half2 p2 = __hadd2(v4, v5);
    const __half2 p3 = __hadd2(v6, v7);
    const __half2 q0 = __hadd2(p0, p1);
    const __half2 q1 = __hadd2(p2, p3);
    return __half22float2(__hadd2(q0, q1));
}

__device__ __forceinline__ float4 reduce8(
    const uint2& u0, const uint2& u1, const uint2& u2, const uint2& u3,
    const uint2& u4, const uint2& u5, const uint2& u6, const uint2& u7,
    const float4& t)
{
    const float2 lo = tree8_h2(as_h2(u0.x), as_h2(u1.x), as_h2(u2.x), as_h2(u3.x),
                               as_h2(u4.x), as_h2(u5.x), as_h2(u6.x), as_h2(u7.x));
    const float2 hi = tree8_h2(as_h2(u0.y), as_h2(u1.y), as_h2(u2.y), as_h2(u3.y),
                               as_h2(u4.y), as_h2(u5.y), as_h2(u6.y), as_h2(u7.y));

    float4 r;
    r.x = fmaxf(t.x + lo.x, 0.0f);
    r.y = fmaxf(t.y + lo.y, 0.0f);
    r.z = fmaxf(t.z + hi.x, 0.0f);
    r.w = fmaxf(t.w + hi.y, 0.0f);
    return r;
}

__global__ void __launch_bounds__(128, 12) fused_gather_kernel(
    const float4* __restrict__ text4,
    const int*    __restrict__ labels,
    float4*       __restrict__ out4)
{
    const int gid = blockIdx.x * blockDim.x + threadIdx.x;   // exact grid

    const int pos = gid >> 5;        // warp-uniform (warp = one position)
    const int d4  = gid & 31;        // uint2 slot 0..31; twin at d4+32

    const int4* lb = reinterpret_cast<const int4*>(labels) + (pos << 1);
    const int4 l0 = __ldg(lb + 0);
    const int4 l1 = __ldg(lb + 1);

    const uint2* __restrict__ Gh = reinterpret_cast<const uint2*>(g_Gh);

    const int idxA = (pos << 6) + d4;        // output float4 index, low half
    const int idxB = idxA + 32;              // high half

    const int b0 = (l0.x << 6) + d4;
    const int b1 = (l0.y << 6) + d4;
    const int b2 = (l0.z << 6) + d4;
    const int b3 = (l0.w << 6) + d4;
    const int b4 = (l1.x << 6) + d4;
    const int b5 = (l1.y << 6) + d4;
    const int b6 = (l1.z << 6) + d4;
    const int b7 = (l1.w << 6) + d4;

    // ---- A-half gathers first...
    const uint2 a0 = __ldg(Gh + b0);
    const uint2 a1 = __ldg(Gh + b1);
    const uint2 a2 = __ldg(Gh + b2);
    const uint2 a3 = __ldg(Gh + b3);
    const uint2 a4 = __ldg(Gh + b4);
    const uint2 a5 = __ldg(Gh + b5);
    const uint2 a6 = __ldg(Gh + b6);
    const uint2 a7 = __ldg(Gh + b7);

    // ...then text (longest latency)...
    const float4 tA = ldlu_f4(text4 + idxA);
    const float4 tB = ldlu_f4(text4 + idxB);

    // ...then C-half gathers; A reduction starts while these are in flight.
    const uint2 c0 = __ldg(Gh + b0 + 32);
    const uint2 c1 = __ldg(Gh + b1 + 32);
    const uint2 c2 = __ldg(Gh + b2 + 32);
    const uint2 c3 = __ldg(Gh + b3 + 32);
    const uint2 c4 = __ldg(Gh + b4 + 32);
    const uint2 c5 = __ldg(Gh + b5 + 32);
    const uint2 c6 = __ldg(Gh + b6 + 32);
    const uint2 c7 = __ldg(Gh + b7 + 32);

    const float4 rA = reduce8(a0, a1, a2, a3, a4, a5, a6, a7, tA);
    __stcs(out4 + idxA, rA);

    const float4 rB = reduce8(c0, c1, c2, c3, c4, c5, c6, c7, tB);
    __stcs(out4 + idxB, rB);
}

// ---------------------------------------------------------------------------
extern "C" void kernel_launch(void* const* d_in, const int* in_sizes, int n_in,
                              void* d_out, int out_size)
{
    const float* text      = (const float*)d_in[0];
    const int*   labels    = (const int*)  d_in[2];
    const float* emb_table = (const float*)d_in[3];
    const float* fc_W      = (const float*)d_in[6];
    const float* fc_b      = (const float*)d_in[7];
    float*       out       = (float*)d_out;

    const int ntotal = in_sizes[0];        // 8,388,608
    const int nhalf  = ntotal / 8;         // 1,048,576 threads (2 float4 each)

    // Max L1D: no smem used by the fused kernel, so request 0% carveout.
    cudaFuncSetAttribute(fused_gather_kernel,
                         cudaFuncAttributePreferredSharedMemoryCarveout, 0);

    build_G_kernel<<<dim3(CN, 4), 256>>>(emb_table, fc_W, fc_b);

    const int block = 128;
    const int grid  = nhalf / block;       // 8192 exactly
    fused_gather_kernel<<<grid, block>>>(
        reinterpret_cast<const float4*>(text),
        labels,
        reinterpret_cast<float4*>(out));
}